// round 15
// baseline (speedup 1.0000x reference)
#include <cuda_runtime.h>
#include <cuda_fp16.h>

#define NN 100000
#define EE 1600000
#define FF 128
#define HH 64
#define H2 (HH / 2)

#define SCAN_B 1024
#define NBLK ((NN + SCAN_B - 1) / SCAN_B)   // 98
#define LINB2 (2 * ((NN + 127) / 128))      // 1564 linear blocks (128 rows, set = bx&1)
#define CNTB  ((2 * EE + 255) / 256)        // 12500 count blocks

// ---------------- device scratch (static; no runtime allocation) ------------
__device__ __half2 g_bufA[NN * H2];    // h1
__device__ __half2 g_bufC[NN * H2];    // h2
__device__ __half2 g_bufD1[NN * H2];   // z1 chain hop1
__device__ __half2 g_bufD2[NN * H2];   // sup chain hop1
__device__ __half2 g_bufD3[NN * H2];   // z2-pri chain hop1
__device__ int     g_cnt[2 * NN];
__device__ float   g_dinv[3 * NN];     // hop-side: p1, p2, sup
__device__ float2  g_dinv12[NN];       // fill-side: {p1, p2} packed
__device__ int     g_rowptr[2 * NN];
__device__ int     g_cursor[2 * NN];
__device__ int     g_bsum[2 * NBLK];
__device__ int4    g_pri_pack[EE];     // {src, c1bits, c2bits, 0}
__device__ int2    g_sup_pack[EE];     // {src, cbits}

// ---------------- combined: linear (blocks [0,LINB2)) + degree count -----------
// Linear split: 128 rows/block, each row handled by a thread PAIR (half = tid>>7,
// 16 u64 accumulators each) -> <=84 regs with launch_bounds(256,3) -> 3 blocks/SM
// for BOTH partitions (count co-residency was 2 blocks/SM at 114 regs).
__global__ void __launch_bounds__(256, 3)
count_linear_kernel(const int* __restrict__ pri,
                    const int* __restrict__ sup,
                    const float* __restrict__ x,
                    const float* __restrict__ w1,
                    const float* __restrict__ b1,
                    const float* __restrict__ w2,
                    const float* __restrict__ b2,
                    __half2* __restrict__ o1,
                    __half2* __restrict__ o2) {
    __shared__ unsigned long long wt2[FF][H2];   // 32 KB
    __shared__ float bs[HH];

    if (blockIdx.x >= LINB2) {
        int i = (blockIdx.x - LINB2) * blockDim.x + threadIdx.x;
        if (i < EE) {
            atomicAdd(&g_cnt[pri[EE + i]], 1);
        } else if (i < 2 * EE) {
            atomicAdd(&g_cnt[NN + sup[i]], 1);
        }
        return;
    }

    int set = blockIdx.x & 1;
    int rowblk = blockIdx.x >> 1;
    const float* w  = set ? w2 : w1;
    const float* b  = set ? b2 : b1;
    __half2* outp   = set ? o2 : o1;

    int tid = threadIdx.x;
    for (int idx = tid; idx < FF * H2; idx += 256) {
        int p = idx & (H2 - 1);
        int f = idx >> 5;
        unsigned long long pk;
        float lo = w[(2 * p) * FF + f];
        float hi = w[(2 * p + 1) * FF + f];
        asm("mov.b64 %0, {%1, %2};" : "=l"(pk) : "f"(lo), "f"(hi));
        wt2[f][p] = pk;
    }
    if (tid < HH) bs[tid] = b[tid];
    __syncthreads();

    int row  = rowblk * 128 + (tid & 127);
    int half = tid >> 7;                 // 0: outputs 0-31, 1: outputs 32-63
    if (row >= NN) return;

    unsigned long long acc2[H2 / 2];     // 16 packed pairs
#pragma unroll
    for (int p = 0; p < H2 / 2; p++) {
        int k = half * 32 + 2 * p;
        asm("mov.b64 %0, {%1, %2};" : "=l"(acc2[p]) : "f"(bs[k]), "f"(bs[k + 1]));
    }

    const float4* xr = reinterpret_cast<const float4*>(x + (size_t)row * FF);
#pragma unroll 2
    for (int f4 = 0; f4 < FF / 4; f4++) {
        float4 xv = xr[f4];
        float xq[4] = {xv.x, xv.y, xv.z, xv.w};
#pragma unroll
        for (int q = 0; q < 4; q++) {
            int f = f4 * 4 + q;
            unsigned long long xx;
            asm("mov.b64 %0, {%1, %1};" : "=l"(xx) : "f"(xq[q]));
            const ulonglong2* wrow =
                reinterpret_cast<const ulonglong2*>(&wt2[f][half * 16]);
#pragma unroll
            for (int k8 = 0; k8 < H2 / 4; k8++) {   // 8 ulonglong2 = 16 pairs
                ulonglong2 wv = wrow[k8];
                asm("fma.rn.f32x2 %0, %1, %2, %0;" : "+l"(acc2[2 * k8])     : "l"(wv.x), "l"(xx));
                asm("fma.rn.f32x2 %0, %1, %2, %0;" : "+l"(acc2[2 * k8 + 1]) : "l"(wv.y), "l"(xx));
            }
        }
    }

    union { __half2 h2[H2 / 2]; uint4 u4[H2 / 8]; } P;
#pragma unroll
    for (int p = 0; p < H2 / 2; p++) {
        float lo, hi;
        asm("mov.b64 {%0, %1}, %2;" : "=f"(lo), "=f"(hi) : "l"(acc2[p]));
        P.h2[p] = __floats2half2_rn(lo, hi);
    }
    uint4* op = reinterpret_cast<uint4*>(outp + (size_t)row * H2 + half * 16);
#pragma unroll
    for (int q = 0; q < H2 / 8; q++) op[q] = P.u4[q];
}

// ---------------- scan part 1 + fused dinv --------------------------------------
__global__ void scan1_kernel() {
    __shared__ int sh[SCAN_B];
    int seg = blockIdx.y;
    int i = blockIdx.x * SCAN_B + threadIdx.x;
    int v = (i < NN) ? g_cnt[seg * NN + i] : 0;

    if (seg == 0 && i < NN) {
        float cp = (float)v;
        float cs = (float)g_cnt[NN + i];
        float d1 = rsqrtf(cp + 0.3f);
        float d2 = rsqrtf(cp + 0.5f);
        g_dinv[i]          = d1;
        g_dinv[NN + i]     = d2;
        g_dinv[2 * NN + i] = rsqrtf(cs + 0.5f);
        g_dinv12[i]        = make_float2(d1, d2);
    }

    sh[threadIdx.x] = v;
    __syncthreads();
    for (int off = 1; off < SCAN_B; off <<= 1) {
        int t = (threadIdx.x >= off) ? sh[threadIdx.x - off] : 0;
        __syncthreads();
        sh[threadIdx.x] += t;
        __syncthreads();
    }
    if (i < NN) g_rowptr[seg * NN + i] = sh[threadIdx.x] - v;
    if (threadIdx.x == SCAN_B - 1) g_bsum[seg * NBLK + blockIdx.x] = sh[threadIdx.x];
}

// ---------------- scan part 2+3 -------------------------------------------------
__global__ void scan23_kernel() {
    int seg = blockIdx.y;
    int t = threadIdx.x;
    __shared__ int warpsum[32];
    __shared__ int soff;

    int p = (t < NBLK && t < blockIdx.x) ? g_bsum[seg * NBLK + t] : 0;
    for (int o = 16; o; o >>= 1) p += __shfl_down_sync(0xffffffffu, p, o);
    if ((t & 31) == 0) warpsum[t >> 5] = p;
    __syncthreads();
    if (t < 32) {
        int v = warpsum[t];
        for (int o = 16; o; o >>= 1) v += __shfl_down_sync(0xffffffffu, v, o);
        if (t == 0) soff = v;
    }
    __syncthreads();

    int i = blockIdx.x * SCAN_B + t;
    if (i < NN) {
        int rp = g_rowptr[seg * NN + i] + soff;
        g_rowptr[seg * NN + i] = rp;
        g_cursor[seg * NN + i] = rp;
    }
}

// ---------------- fill (standalone: low regs, high occupancy) -------------------
__global__ void fill_kernel(const int* __restrict__ pri,
                            const int* __restrict__ sup) {
    int i = blockIdx.x * blockDim.x + threadIdx.x;
    if (i < EE) {
        int r = pri[i], c = pri[EE + i];
        int pos = atomicAdd(&g_cursor[c], 1);
        float2 d = g_dinv12[r];
        g_pri_pack[pos] = make_int4(r, __float_as_int(d.x), __float_as_int(d.y), 0);
    } else if (i < 2 * EE) {
        int e = i - EE;
        int r = sup[e], c = sup[EE + e];
        int pos = atomicAdd(&g_cursor[NN + c], 1);
        g_sup_pack[pos] = make_int2(r, __float_as_int(g_dinv[2 * NN + r]));
    }
}

// ---------------- hop helpers ---------------------------------------------------
__device__ __forceinline__ void acc_row(float2 (&acc)[4], uint4 v, float cf) {
    union { uint4 u; __half2 h2[4]; } U; U.u = v;
#pragma unroll
    for (int q = 0; q < 4; q++) {
        float2 f = __half22float2(U.h2[q]);
        acc[q].x += cf * f.x;
        acc[q].y += cf * f.y;
    }
}
__device__ __forceinline__ void self_scale(float2 (&acc)[4], uint4 v, float s) {
    union { uint4 u; __half2 h2[4]; } U; U.u = v;
#pragma unroll
    for (int q = 0; q < 4; q++) {
        float2 f = __half22float2(U.h2[q]);
        acc[q].x = s * f.x;
        acc[q].y = s * f.y;
    }
}
__device__ __forceinline__ uint4 pack_row(const float2 (&acc)[4]) {
    union { __half2 h2[4]; uint4 u; } P;
#pragma unroll
    for (int q = 0; q < 4; q++) P.h2[q] = __float22half2_rn(acc[q]);
    return P.u;
}

// ---------------- P1: hop1 (R11 version: no prefetch, plain buffers) -------------
struct FusedArgs {
    const int4* pack;
    const int*  rowptr;
    const int*  cnt;
    const float* dinvA;
    const float* dinvC;
    const uint4* hA;
    const uint4* hC;
    uint4* outA;
    uint4* outC;
};
struct SupArgs {
    const int2* pack;
    const int*  rowptr;
    const int*  cnt;
    const float* dinv;
    const uint4* h;
    uint4* out;
};

__device__ __forceinline__ void hop1_fused(const FusedArgs A) {
    int warp = blockIdx.x * (blockDim.x >> 5) + (threadIdx.x >> 5);
    int lane = threadIdx.x & 31;
    int g = lane >> 3, i = lane & 7;
    int c = warp * 4 + g;

    float dcA = A.dinvA[c], dcC = A.dinvC[c];
    float sA = 0.7f + 0.3f * dcA * dcA;
    float sC = 0.5f + 0.5f * dcC * dcC;

    float2 accA[4], accC[4];
    self_scale(accA, A.hA[(size_t)c * 8 + i], sA);
    self_scale(accC, A.hC[(size_t)c * 8 + i], sC);

    int start = A.rowptr[c];
    int n = A.cnt[c];
    int nmax = __reduce_max_sync(0xffffffffu, n);

    for (int base = 0; base < nmax; base += 8) {
        int4 e = make_int4(0, 0, 0, 0);
        if (i < n - base) e = A.pack[start + base + i];
        int jmax = nmax - base;
        if (jmax >= 8) {
#pragma unroll
            for (int j = 0; j < 8; j++) {
                int   rj  = __shfl_sync(0xffffffffu, e.x, j, 8);
                float cf1 = __int_as_float(__shfl_sync(0xffffffffu, e.y, j, 8)) * dcA;
                float cf2 = __int_as_float(__shfl_sync(0xffffffffu, e.z, j, 8)) * dcC;
                uint4 vA = A.hA[(size_t)rj * 8 + i];
                uint4 vC = A.hC[(size_t)rj * 8 + i];
                acc_row(accA, vA, cf1);
                acc_row(accC, vC, cf2);
            }
        } else {
            for (int j = 0; j < jmax; j++) {
                int   rj  = __shfl_sync(0xffffffffu, e.x, j, 8);
                float cf1 = __int_as_float(__shfl_sync(0xffffffffu, e.y, j, 8)) * dcA;
                float cf2 = __int_as_float(__shfl_sync(0xffffffffu, e.z, j, 8)) * dcC;
                uint4 vA = A.hA[(size_t)rj * 8 + i];
                uint4 vC = A.hC[(size_t)rj * 8 + i];
                acc_row(accA, vA, cf1);
                acc_row(accC, vC, cf2);
            }
        }
    }

    A.outA[(size_t)c * 8 + i] = pack_row(accA);
    A.outC[(size_t)c * 8 + i] = pack_row(accC);
}

__device__ __forceinline__ void hop1_sup(const SupArgs A) {
    int warp = blockIdx.x * (blockDim.x >> 5) + (threadIdx.x >> 5);
    int lane = threadIdx.x & 31;
    int g = lane >> 3, i = lane & 7;
    int c = warp * 4 + g;

    float dc = A.dinv[c];
    float s = 0.5f + 0.5f * dc * dc;

    float2 acc[4];
    self_scale(acc, A.h[(size_t)c * 8 + i], s);

    int start = A.rowptr[c];
    int n = A.cnt[c];
    int nmax = __reduce_max_sync(0xffffffffu, n);

    for (int base = 0; base < nmax; base += 8) {
        int2 e = make_int2(0, 0);
        if (i < n - base) e = A.pack[start + base + i];
        int jmax = nmax - base;
        if (jmax >= 8) {
#pragma unroll
            for (int j = 0; j < 8; j++) {
                int   rj = __shfl_sync(0xffffffffu, e.x, j, 8);
                float cf = __int_as_float(__shfl_sync(0xffffffffu, e.y, j, 8)) * dc;
                uint4 v = A.h[(size_t)rj * 8 + i];
                acc_row(acc, v, cf);
            }
        } else {
            for (int j = 0; j < jmax; j++) {
                int   rj = __shfl_sync(0xffffffffu, e.x, j, 8);
                float cf = __int_as_float(__shfl_sync(0xffffffffu, e.y, j, 8)) * dc;
                uint4 v = A.h[(size_t)rj * 8 + i];
                acc_row(acc, v, cf);
            }
        }
    }

    A.out[(size_t)c * 8 + i] = pack_row(acc);
}

__global__ void hop1_kernel(FusedArgs fa, SupArgs sa) {
    if (blockIdx.y == 0) hop1_fused(fa);
    else                 hop1_sup(sa);
}

// ---------------- P2: hop2, direct fp32 output ----------------------------------
__global__ void hop2_kernel(const int4* __restrict__ ppack,
                            const int*  __restrict__ prp,
                            const int*  __restrict__ pcnt,
                            const int2* __restrict__ spack,
                            const int*  __restrict__ srp,
                            const int*  __restrict__ scnt,
                            const float* __restrict__ dinv,
                            const uint4* __restrict__ hD1,
                            const uint4* __restrict__ hD3,
                            const uint4* __restrict__ hD2,
                            float* __restrict__ z1,
                            float* __restrict__ z2) {
    int warp = blockIdx.x * (blockDim.x >> 5) + (threadIdx.x >> 5);
    int lane = threadIdx.x & 31;
    int g = lane >> 3, i = lane & 7;
    int c = warp * 4 + g;

    float dcA = dinv[c];
    float dcC = dinv[NN + c];
    float dcS = dinv[2 * NN + c];
    float sA = 0.7f + 0.3f * dcA * dcA;
    float sC = 0.5f + 0.5f * dcC * dcC;
    float sS = 0.5f + 0.5f * dcS * dcS;

    float2 accA[4], accC[4];
    self_scale(accA, hD1[(size_t)c * 8 + i], sA);
    self_scale(accC, hD3[(size_t)c * 8 + i], sC);

    {
        int start = prp[c];
        int n = pcnt[c];
        int nmax = __reduce_max_sync(0xffffffffu, n);
        for (int base = 0; base < nmax; base += 8) {
            int4 e = make_int4(0, 0, 0, 0);
            if (i < n - base) e = ppack[start + base + i];
            int jmax = nmax - base;
            if (jmax >= 8) {
#pragma unroll
                for (int j = 0; j < 8; j++) {
                    int   rj  = __shfl_sync(0xffffffffu, e.x, j, 8);
                    float cf1 = __int_as_float(__shfl_sync(0xffffffffu, e.y, j, 8)) * dcA;
                    float cf2 = __int_as_float(__shfl_sync(0xffffffffu, e.z, j, 8)) * dcC;
                    uint4 vA = hD1[(size_t)rj * 8 + i];
                    uint4 vC = hD3[(size_t)rj * 8 + i];
                    acc_row(accA, vA, cf1);
                    acc_row(accC, vC, cf2);
                }
            } else {
                for (int j = 0; j < jmax; j++) {
                    int   rj  = __shfl_sync(0xffffffffu, e.x, j, 8);
                    float cf1 = __int_as_float(__shfl_sync(0xffffffffu, e.y, j, 8)) * dcA;
                    float cf2 = __int_as_float(__shfl_sync(0xffffffffu, e.z, j, 8)) * dcC;
                    uint4 vA = hD1[(size_t)rj * 8 + i];
                    uint4 vC = hD3[(size_t)rj * 8 + i];
                    acc_row(accA, vA, cf1);
                    acc_row(accC, vC, cf2);
                }
            }
        }
    }

    {
        float4* op = reinterpret_cast<float4*>(z1 + (size_t)c * HH + i * 8);
        op[0] = make_float4(accA[0].x, accA[0].y, accA[1].x, accA[1].y);
        op[1] = make_float4(accA[2].x, accA[2].y, accA[3].x, accA[3].y);
    }

    {
        float2 accS[4];
        self_scale(accS, hD2[(size_t)c * 8 + i], sS);

        int start = srp[c];
        int n = scnt[c];
        int nmax = __reduce_max_sync(0xffffffffu, n);
        for (int base = 0; base < nmax; base += 8) {
            int2 e = make_int2(0, 0);
            if (i < n - base) e = spack[start + base + i];
            int jmax = nmax - base;
            if (jmax >= 8) {
#pragma unroll
                for (int j = 0; j < 8; j++) {
                    int   rj = __shfl_sync(0xffffffffu, e.x, j, 8);
                    float cf = __int_as_float(__shfl_sync(0xffffffffu, e.y, j, 8)) * dcS;
                    uint4 v = hD2[(size_t)rj * 8 + i];
                    acc_row(accS, v, cf);
                }
            } else {
                for (int j = 0; j < jmax; j++) {
                    int   rj = __shfl_sync(0xffffffffu, e.x, j, 8);
                    float cf = __int_as_float(__shfl_sync(0xffffffffu, e.y, j, 8)) * dcS;
                    uint4 v = hD2[(size_t)rj * 8 + i];
                    acc_row(accS, v, cf);
                }
            }
        }

#pragma unroll
        for (int q = 0; q < 4; q++) {
            accC[q].x += accS[q].x;
            accC[q].y += accS[q].y;
        }
    }

    {
        float4* op = reinterpret_cast<float4*>(z2 + (size_t)c * HH + i * 8);
        op[0] = make_float4(accC[0].x, accC[0].y, accC[1].x, accC[1].y);
        op[1] = make_float4(accC[2].x, accC[2].y, accC[3].x, accC[3].y);
    }
}

// ---------------- launch --------------------------------------------------------
extern "C" void kernel_launch(void* const* d_in, const int* in_sizes, int n_in,
                              void* d_out, int out_size) {
    const float* x   = (const float*)d_in[0];
    const int*   pri = (const int*)d_in[1];
    const int*   sup = (const int*)d_in[2];
    const float* w1  = (const float*)d_in[3];
    const float* b1  = (const float*)d_in[4];
    const float* w2  = (const float*)d_in[5];
    const float* b2  = (const float*)d_in[6];
    float* out = (float*)d_out;

    __half2 *bufA, *bufC, *bufD1, *bufD2, *bufD3;
    float *dinv;
    int *cnt, *rowptr;
    int4 *pri_pack;
    int2 *sup_pack;
    cudaGetSymbolAddress((void**)&bufA, g_bufA);
    cudaGetSymbolAddress((void**)&bufC, g_bufC);
    cudaGetSymbolAddress((void**)&bufD1, g_bufD1);
    cudaGetSymbolAddress((void**)&bufD2, g_bufD2);
    cudaGetSymbolAddress((void**)&bufD3, g_bufD3);
    cudaGetSymbolAddress((void**)&dinv, g_dinv);
    cudaGetSymbolAddress((void**)&cnt, g_cnt);
    cudaGetSymbolAddress((void**)&rowptr, g_rowptr);
    cudaGetSymbolAddress((void**)&pri_pack, g_pri_pack);
    cudaGetSymbolAddress((void**)&sup_pack, g_sup_pack);

    const int TPB = 256;

    cudaMemsetAsync(cnt, 0, 2 * NN * sizeof(int));

    // combined linear + degree count (R11 pairing; linear now 3 blocks/SM)
    count_linear_kernel<<<LINB2 + CNTB, TPB>>>(pri, sup, x, w1, b1, w2, b2,
                                               bufA, bufC);

    scan1_kernel<<<dim3(NBLK, 2), SCAN_B>>>();
    scan23_kernel<<<dim3(NBLK, 2), SCAN_B>>>();
    fill_kernel<<<CNTB, TPB>>>(pri, sup);

    float* z1 = out;
    float* z2 = out + (size_t)NN * HH;
    const int gridHopX = NN / 32;

    FusedArgs f1 = {pri_pack, rowptr, cnt, dinv, dinv + NN,
                    (const uint4*)bufA, (const uint4*)bufC,
                    (uint4*)bufD1, (uint4*)bufD3};
    SupArgs   s1 = {sup_pack, rowptr + NN, cnt + NN, dinv + 2 * NN,
                    (const uint4*)bufC, (uint4*)bufD2};
    hop1_kernel<<<dim3(gridHopX, 2), TPB>>>(f1, s1);

    hop2_kernel<<<gridHopX, TPB>>>(pri_pack, rowptr, cnt,
                                   sup_pack, rowptr + NN, cnt + NN,
                                   dinv,
                                   (const uint4*)bufD1, (const uint4*)bufD3,
                                   (const uint4*)bufD2,
                                   z1, z2);
}

// round 16
// speedup vs baseline: 1.0976x; 1.0976x over previous
#include <cuda_runtime.h>
#include <cuda_fp16.h>

#define NN 100000
#define EE 1600000
#define FF 128
#define HH 64
#define H2 (HH / 2)

#define SCAN_B 1024
#define NBLK ((NN + SCAN_B - 1) / SCAN_B)   // 98
#define LINB  (2 * ((NN + 255) / 256))      // 782 linear blocks (set = bx&1)
#define CNTB  ((2 * EE + 255) / 256)        // 12500 count blocks

// ---------------- device scratch (static; no runtime allocation) ------------
__device__ __half2 g_bufA[NN * H2];    // h1
__device__ __half2 g_bufC[NN * H2];    // h2
__device__ __half2 g_bufD1[NN * H2];   // z1 chain hop1
__device__ __half2 g_bufD2[NN * H2];   // sup chain hop1
__device__ __half2 g_bufD3[NN * H2];   // z2-pri chain hop1
__device__ int     g_cnt[2 * NN];
__device__ float   g_dinv[3 * NN];     // hop-side: p1, p2, sup
__device__ float2  g_dinv12[NN];       // fill-side: {p1, p2} packed
__device__ int     g_rowptr[2 * NN];
__device__ int     g_cursor[2 * NN];
__device__ int     g_bsum[2 * NBLK];
__device__ int4    g_pri_pack[EE];     // {src, c1bits, c2bits, 0}
__device__ int2    g_sup_pack[EE];     // {src, cbits}

// ---------------- combined: linear (blocks [0,LINB)) + degree count ------------
// R11 pairing (validated best): linear 256 rows/block, one thread per row,
// 114 regs; count blocks tolerate the occupancy hit. Never pair with fill (R12),
// never split rows across thread pairs (R15: smem fill cost doubled).
__global__ void count_linear_kernel(const int* __restrict__ pri,
                                    const int* __restrict__ sup,
                                    const float* __restrict__ x,
                                    const float* __restrict__ w1,
                                    const float* __restrict__ b1,
                                    const float* __restrict__ w2,
                                    const float* __restrict__ b2,
                                    __half2* __restrict__ o1,
                                    __half2* __restrict__ o2) {
    __shared__ unsigned long long wt2[FF][H2];   // 32 KB
    __shared__ float bs[HH];

    if (blockIdx.x >= LINB) {
        int i = (blockIdx.x - LINB) * blockDim.x + threadIdx.x;
        if (i < EE) {
            atomicAdd(&g_cnt[pri[EE + i]], 1);
        } else if (i < 2 * EE) {
            atomicAdd(&g_cnt[NN + sup[i]], 1);
        }
        return;
    }

    int set = blockIdx.x & 1;
    int rowblk = blockIdx.x >> 1;
    const float* w  = set ? w2 : w1;
    const float* b  = set ? b2 : b1;
    __half2* outp   = set ? o2 : o1;

    int tid = threadIdx.x;
    for (int idx = tid; idx < FF * H2; idx += 256) {
        int p = idx & (H2 - 1);
        int f = idx >> 5;
        unsigned long long pk;
        float lo = w[(2 * p) * FF + f];
        float hi = w[(2 * p + 1) * FF + f];
        asm("mov.b64 %0, {%1, %2};" : "=l"(pk) : "f"(lo), "f"(hi));
        wt2[f][p] = pk;
    }
    if (tid < HH) bs[tid] = b[tid];
    __syncthreads();

    int row = rowblk * 256 + tid;
    if (row >= NN) return;

    unsigned long long acc2[H2];
#pragma unroll
    for (int p = 0; p < H2; p++)
        asm("mov.b64 %0, {%1, %2};" : "=l"(acc2[p]) : "f"(bs[2 * p]), "f"(bs[2 * p + 1]));

    const float4* xr = reinterpret_cast<const float4*>(x + (size_t)row * FF);
#pragma unroll 2
    for (int f4 = 0; f4 < FF / 4; f4++) {
        float4 xv = xr[f4];
        float xq[4] = {xv.x, xv.y, xv.z, xv.w};
#pragma unroll
        for (int q = 0; q < 4; q++) {
            int f = f4 * 4 + q;
            unsigned long long xx;
            asm("mov.b64 %0, {%1, %1};" : "=l"(xx) : "f"(xq[q]));
            const ulonglong2* wrow = reinterpret_cast<const ulonglong2*>(&wt2[f][0]);
#pragma unroll
            for (int k8 = 0; k8 < H2 / 2; k8++) {
                ulonglong2 wv = wrow[k8];
                asm("fma.rn.f32x2 %0, %1, %2, %0;" : "+l"(acc2[2 * k8])     : "l"(wv.x), "l"(xx));
                asm("fma.rn.f32x2 %0, %1, %2, %0;" : "+l"(acc2[2 * k8 + 1]) : "l"(wv.y), "l"(xx));
            }
        }
    }

    union { __half2 h2[H2]; uint4 u4[H2 / 4]; } P;
#pragma unroll
    for (int p = 0; p < H2; p++) {
        float lo, hi;
        asm("mov.b64 {%0, %1}, %2;" : "=f"(lo), "=f"(hi) : "l"(acc2[p]));
        P.h2[p] = __floats2half2_rn(lo, hi);
    }
    uint4* op = reinterpret_cast<uint4*>(outp + (size_t)row * H2);
#pragma unroll
    for (int q = 0; q < H2 / 4; q++) op[q] = P.u4[q];
}

// ---------------- scan part 1 + fused dinv --------------------------------------
__global__ void scan1_kernel() {
    __shared__ int sh[SCAN_B];
    int seg = blockIdx.y;
    int i = blockIdx.x * SCAN_B + threadIdx.x;
    int v = (i < NN) ? g_cnt[seg * NN + i] : 0;

    if (seg == 0 && i < NN) {
        float cp = (float)v;
        float cs = (float)g_cnt[NN + i];
        float d1 = rsqrtf(cp + 0.3f);
        float d2 = rsqrtf(cp + 0.5f);
        g_dinv[i]          = d1;
        g_dinv[NN + i]     = d2;
        g_dinv[2 * NN + i] = rsqrtf(cs + 0.5f);
        g_dinv12[i]        = make_float2(d1, d2);
    }

    sh[threadIdx.x] = v;
    __syncthreads();
    for (int off = 1; off < SCAN_B; off <<= 1) {
        int t = (threadIdx.x >= off) ? sh[threadIdx.x - off] : 0;
        __syncthreads();
        sh[threadIdx.x] += t;
        __syncthreads();
    }
    if (i < NN) g_rowptr[seg * NN + i] = sh[threadIdx.x] - v;
    if (threadIdx.x == SCAN_B - 1) g_bsum[seg * NBLK + blockIdx.x] = sh[threadIdx.x];
}

// ---------------- scan part 2+3 -------------------------------------------------
__global__ void scan23_kernel() {
    int seg = blockIdx.y;
    int t = threadIdx.x;
    __shared__ int warpsum[32];
    __shared__ int soff;

    int p = (t < NBLK && t < blockIdx.x) ? g_bsum[seg * NBLK + t] : 0;
    for (int o = 16; o; o >>= 1) p += __shfl_down_sync(0xffffffffu, p, o);
    if ((t & 31) == 0) warpsum[t >> 5] = p;
    __syncthreads();
    if (t < 32) {
        int v = warpsum[t];
        for (int o = 16; o; o >>= 1) v += __shfl_down_sync(0xffffffffu, v, o);
        if (t == 0) soff = v;
    }
    __syncthreads();

    int i = blockIdx.x * SCAN_B + t;
    if (i < NN) {
        int rp = g_rowptr[seg * NN + i] + soff;
        g_rowptr[seg * NN + i] = rp;
        g_cursor[seg * NN + i] = rp;
    }
}

// ---------------- fill (standalone; dinv12 packed load on pri branch) -----------
__global__ void fill_kernel(const int* __restrict__ pri,
                            const int* __restrict__ sup) {
    int i = blockIdx.x * blockDim.x + threadIdx.x;
    if (i < EE) {
        int r = pri[i], c = pri[EE + i];
        int pos = atomicAdd(&g_cursor[c], 1);
        float2 d = g_dinv12[r];
        g_pri_pack[pos] = make_int4(r, __float_as_int(d.x), __float_as_int(d.y), 0);
    } else if (i < 2 * EE) {
        int e = i - EE;
        int r = sup[e], c = sup[EE + e];
        int pos = atomicAdd(&g_cursor[NN + c], 1);
        g_sup_pack[pos] = make_int2(r, __float_as_int(g_dinv[2 * NN + r]));
    }
}

// ---------------- hop helpers ---------------------------------------------------
__device__ __forceinline__ void acc_row(float2 (&acc)[4], uint4 v, float cf) {
    union { uint4 u; __half2 h2[4]; } U; U.u = v;
#pragma unroll
    for (int q = 0; q < 4; q++) {
        float2 f = __half22float2(U.h2[q]);
        acc[q].x += cf * f.x;
        acc[q].y += cf * f.y;
    }
}
__device__ __forceinline__ void self_scale(float2 (&acc)[4], uint4 v, float s) {
    union { uint4 u; __half2 h2[4]; } U; U.u = v;
#pragma unroll
    for (int q = 0; q < 4; q++) {
        float2 f = __half22float2(U.h2[q]);
        acc[q].x = s * f.x;
        acc[q].y = s * f.y;
    }
}
__device__ __forceinline__ uint4 pack_row(const float2 (&acc)[4]) {
    union { __half2 h2[4]; uint4 u; } P;
#pragma unroll
    for (int q = 0; q < 4; q++) P.h2[q] = __float22half2_rn(acc[q]);
    return P.u;
}

// ---------------- P1: hop1 -------------------------------------------------------
struct FusedArgs {
    const int4* pack;
    const int*  rowptr;
    const int*  cnt;
    const float* dinvA;
    const float* dinvC;
    const uint4* hA;
    const uint4* hC;
    uint4* outA;
    uint4* outC;
};
struct SupArgs {
    const int2* pack;
    const int*  rowptr;
    const int*  cnt;
    const float* dinv;
    const uint4* h;
    uint4* out;
};

__device__ __forceinline__ void hop1_fused(const FusedArgs A) {
    int warp = blockIdx.x * (blockDim.x >> 5) + (threadIdx.x >> 5);
    int lane = threadIdx.x & 31;
    int g = lane >> 3, i = lane & 7;
    int c = warp * 4 + g;

    float dcA = A.dinvA[c], dcC = A.dinvC[c];
    float sA = 0.7f + 0.3f * dcA * dcA;
    float sC = 0.5f + 0.5f * dcC * dcC;

    float2 accA[4], accC[4];
    self_scale(accA, A.hA[(size_t)c * 8 + i], sA);
    self_scale(accC, A.hC[(size_t)c * 8 + i], sC);

    int start = A.rowptr[c];
    int n = A.cnt[c];
    int nmax = __reduce_max_sync(0xffffffffu, n);

    for (int base = 0; base < nmax; base += 8) {
        int4 e = make_int4(0, 0, 0, 0);
        if (i < n - base) e = A.pack[start + base + i];
        int jmax = nmax - base;
        if (jmax >= 8) {
#pragma unroll
            for (int j = 0; j < 8; j++) {
                int   rj  = __shfl_sync(0xffffffffu, e.x, j, 8);
                float cf1 = __int_as_float(__shfl_sync(0xffffffffu, e.y, j, 8)) * dcA;
                float cf2 = __int_as_float(__shfl_sync(0xffffffffu, e.z, j, 8)) * dcC;
                uint4 vA = A.hA[(size_t)rj * 8 + i];
                uint4 vC = A.hC[(size_t)rj * 8 + i];
                acc_row(accA, vA, cf1);
                acc_row(accC, vC, cf2);
            }
        } else {
            for (int j = 0; j < jmax; j++) {
                int   rj  = __shfl_sync(0xffffffffu, e.x, j, 8);
                float cf1 = __int_as_float(__shfl_sync(0xffffffffu, e.y, j, 8)) * dcA;
                float cf2 = __int_as_float(__shfl_sync(0xffffffffu, e.z, j, 8)) * dcC;
                uint4 vA = A.hA[(size_t)rj * 8 + i];
                uint4 vC = A.hC[(size_t)rj * 8 + i];
                acc_row(accA, vA, cf1);
                acc_row(accC, vC, cf2);
            }
        }
    }

    A.outA[(size_t)c * 8 + i] = pack_row(accA);
    A.outC[(size_t)c * 8 + i] = pack_row(accC);
}

__device__ __forceinline__ void hop1_sup(const SupArgs A) {
    int warp = blockIdx.x * (blockDim.x >> 5) + (threadIdx.x >> 5);
    int lane = threadIdx.x & 31;
    int g = lane >> 3, i = lane & 7;
    int c = warp * 4 + g;

    float dc = A.dinv[c];
    float s = 0.5f + 0.5f * dc * dc;

    float2 acc[4];
    self_scale(acc, A.h[(size_t)c * 8 + i], s);

    int start = A.rowptr[c];
    int n = A.cnt[c];
    int nmax = __reduce_max_sync(0xffffffffu, n);

    for (int base = 0; base < nmax; base += 8) {
        int2 e = make_int2(0, 0);
        if (i < n - base) e = A.pack[start + base + i];
        int jmax = nmax - base;
        if (jmax >= 8) {
#pragma unroll
            for (int j = 0; j < 8; j++) {
                int   rj = __shfl_sync(0xffffffffu, e.x, j, 8);
                float cf = __int_as_float(__shfl_sync(0xffffffffu, e.y, j, 8)) * dc;
                uint4 v = A.h[(size_t)rj * 8 + i];
                acc_row(acc, v, cf);
            }
        } else {
            for (int j = 0; j < jmax; j++) {
                int   rj = __shfl_sync(0xffffffffu, e.x, j, 8);
                float cf = __int_as_float(__shfl_sync(0xffffffffu, e.y, j, 8)) * dc;
                uint4 v = A.h[(size_t)rj * 8 + i];
                acc_row(acc, v, cf);
            }
        }
    }

    A.out[(size_t)c * 8 + i] = pack_row(acc);
}

__global__ void hop1_kernel(FusedArgs fa, SupArgs sa) {
    if (blockIdx.y == 0) hop1_fused(fa);
    else                 hop1_sup(sa);
}

// ---------------- P2: hop2, direct fp32 output ----------------------------------
__global__ void hop2_kernel(const int4* __restrict__ ppack,
                            const int*  __restrict__ prp,
                            const int*  __restrict__ pcnt,
                            const int2* __restrict__ spack,
                            const int*  __restrict__ srp,
                            const int*  __restrict__ scnt,
                            const float* __restrict__ dinv,
                            const uint4* __restrict__ hD1,
                            const uint4* __restrict__ hD3,
                            const uint4* __restrict__ hD2,
                            float* __restrict__ z1,
                            float* __restrict__ z2) {
    int warp = blockIdx.x * (blockDim.x >> 5) + (threadIdx.x >> 5);
    int lane = threadIdx.x & 31;
    int g = lane >> 3, i = lane & 7;
    int c = warp * 4 + g;

    float dcA = dinv[c];
    float dcC = dinv[NN + c];
    float dcS = dinv[2 * NN + c];
    float sA = 0.7f + 0.3f * dcA * dcA;
    float sC = 0.5f + 0.5f * dcC * dcC;
    float sS = 0.5f + 0.5f * dcS * dcS;

    float2 accA[4], accC[4];
    self_scale(accA, hD1[(size_t)c * 8 + i], sA);
    self_scale(accC, hD3[(size_t)c * 8 + i], sC);

    {
        int start = prp[c];
        int n = pcnt[c];
        int nmax = __reduce_max_sync(0xffffffffu, n);
        for (int base = 0; base < nmax; base += 8) {
            int4 e = make_int4(0, 0, 0, 0);
            if (i < n - base) e = ppack[start + base + i];
            int jmax = nmax - base;
            if (jmax >= 8) {
#pragma unroll
                for (int j = 0; j < 8; j++) {
                    int   rj  = __shfl_sync(0xffffffffu, e.x, j, 8);
                    float cf1 = __int_as_float(__shfl_sync(0xffffffffu, e.y, j, 8)) * dcA;
                    float cf2 = __int_as_float(__shfl_sync(0xffffffffu, e.z, j, 8)) * dcC;
                    uint4 vA = hD1[(size_t)rj * 8 + i];
                    uint4 vC = hD3[(size_t)rj * 8 + i];
                    acc_row(accA, vA, cf1);
                    acc_row(accC, vC, cf2);
                }
            } else {
                for (int j = 0; j < jmax; j++) {
                    int   rj  = __shfl_sync(0xffffffffu, e.x, j, 8);
                    float cf1 = __int_as_float(__shfl_sync(0xffffffffu, e.y, j, 8)) * dcA;
                    float cf2 = __int_as_float(__shfl_sync(0xffffffffu, e.z, j, 8)) * dcC;
                    uint4 vA = hD1[(size_t)rj * 8 + i];
                    uint4 vC = hD3[(size_t)rj * 8 + i];
                    acc_row(accA, vA, cf1);
                    acc_row(accC, vC, cf2);
                }
            }
        }
    }

    {
        float4* op = reinterpret_cast<float4*>(z1 + (size_t)c * HH + i * 8);
        op[0] = make_float4(accA[0].x, accA[0].y, accA[1].x, accA[1].y);
        op[1] = make_float4(accA[2].x, accA[2].y, accA[3].x, accA[3].y);
    }

    {
        float2 accS[4];
        self_scale(accS, hD2[(size_t)c * 8 + i], sS);

        int start = srp[c];
        int n = scnt[c];
        int nmax = __reduce_max_sync(0xffffffffu, n);
        for (int base = 0; base < nmax; base += 8) {
            int2 e = make_int2(0, 0);
            if (i < n - base) e = spack[start + base + i];
            int jmax = nmax - base;
            if (jmax >= 8) {
#pragma unroll
                for (int j = 0; j < 8; j++) {
                    int   rj = __shfl_sync(0xffffffffu, e.x, j, 8);
                    float cf = __int_as_float(__shfl_sync(0xffffffffu, e.y, j, 8)) * dcS;
                    uint4 v = hD2[(size_t)rj * 8 + i];
                    acc_row(accS, v, cf);
                }
            } else {
                for (int j = 0; j < jmax; j++) {
                    int   rj = __shfl_sync(0xffffffffu, e.x, j, 8);
                    float cf = __int_as_float(__shfl_sync(0xffffffffu, e.y, j, 8)) * dcS;
                    uint4 v = hD2[(size_t)rj * 8 + i];
                    acc_row(accS, v, cf);
                }
            }
        }

#pragma unroll
        for (int q = 0; q < 4; q++) {
            accC[q].x += accS[q].x;
            accC[q].y += accS[q].y;
        }
    }

    {
        float4* op = reinterpret_cast<float4*>(z2 + (size_t)c * HH + i * 8);
        op[0] = make_float4(accC[0].x, accC[0].y, accC[1].x, accC[1].y);
        op[1] = make_float4(accC[2].x, accC[2].y, accC[3].x, accC[3].y);
    }
}

// ---------------- launch --------------------------------------------------------
extern "C" void kernel_launch(void* const* d_in, const int* in_sizes, int n_in,
                              void* d_out, int out_size) {
    const float* x   = (const float*)d_in[0];
    const int*   pri = (const int*)d_in[1];
    const int*   sup = (const int*)d_in[2];
    const float* w1  = (const float*)d_in[3];
    const float* b1  = (const float*)d_in[4];
    const float* w2  = (const float*)d_in[5];
    const float* b2  = (const float*)d_in[6];
    float* out = (float*)d_out;

    __half2 *bufA, *bufC, *bufD1, *bufD2, *bufD3;
    float *dinv;
    int *cnt, *rowptr;
    int4 *pri_pack;
    int2 *sup_pack;
    cudaGetSymbolAddress((void**)&bufA, g_bufA);
    cudaGetSymbolAddress((void**)&bufC, g_bufC);
    cudaGetSymbolAddress((void**)&bufD1, g_bufD1);
    cudaGetSymbolAddress((void**)&bufD2, g_bufD2);
    cudaGetSymbolAddress((void**)&bufD3, g_bufD3);
    cudaGetSymbolAddress((void**)&dinv, g_dinv);
    cudaGetSymbolAddress((void**)&cnt, g_cnt);
    cudaGetSymbolAddress((void**)&rowptr, g_rowptr);
    cudaGetSymbolAddress((void**)&pri_pack, g_pri_pack);
    cudaGetSymbolAddress((void**)&sup_pack, g_sup_pack);

    const int TPB = 256;

    cudaMemsetAsync(cnt, 0, 2 * NN * sizeof(int));

    // combined linear + degree count (validated R11 pairing)
    count_linear_kernel<<<LINB + CNTB, TPB>>>(pri, sup, x, w1, b1, w2, b2,
                                              bufA, bufC);

    scan1_kernel<<<dim3(NBLK, 2), SCAN_B>>>();
    scan23_kernel<<<dim3(NBLK, 2), SCAN_B>>>();
    fill_kernel<<<CNTB, TPB>>>(pri, sup);

    float* z1 = out;
    float* z2 = out + (size_t)NN * HH;
    const int gridHopX = NN / 32;

    FusedArgs f1 = {pri_pack, rowptr, cnt, dinv, dinv + NN,
                    (const uint4*)bufA, (const uint4*)bufC,
                    (uint4*)bufD1, (uint4*)bufD3};
    SupArgs   s1 = {sup_pack, rowptr + NN, cnt + NN, dinv + 2 * NN,
                    (const uint4*)bufC, (uint4*)bufD2};
    hop1_kernel<<<dim3(gridHopX, 2), TPB>>>(f1, s1);

    hop2_kernel<<<gridHopX, TPB>>>(pri_pack, rowptr, cnt,
                                   sup_pack, rowptr + NN, cnt + NN,
                                   dinv,
                                   (const uint4*)bufD1, (const uint4*)bufD3,
                                   (const uint4*)bufD2,
                                   z1, z2);
}

// round 17
// speedup vs baseline: 1.0984x; 1.0007x over previous
#include <cuda_runtime.h>
#include <cuda_fp16.h>

#define NN 100000
#define EE 1600000
#define FF 128
#define HH 64
#define H2 (HH / 2)

#define SCAN_B 1024
#define NBLK ((NN + SCAN_B - 1) / SCAN_B)   // 98
#define LINB  (2 * ((NN + 255) / 256))      // 782 linear blocks (set = bx&1)
#define CNTB  ((2 * EE + 255) / 256)        // 12500 count blocks

// ---------------- device scratch (static; no runtime allocation) ------------
__device__ __half2 g_bufA[NN * H2];    // h1
__device__ __half2 g_bufC[NN * H2];    // h2
__device__ __half2 g_bufD1[NN * H2];   // z1 chain hop1
__device__ __half2 g_bufD2[NN * H2];   // sup chain hop1
__device__ __half2 g_bufD3[NN * H2];   // z2-pri chain hop1
__device__ int     g_cnt[2 * NN];
__device__ float   g_dinv[3 * NN];     // hop-side: p1, p2, sup
__device__ unsigned g_dinvh[NN];       // fill-side: half2{p1, p2} packed in 4 B
__device__ int     g_rowptr[2 * NN];
__device__ int     g_cursor[2 * NN];
__device__ int     g_bsum[2 * NBLK];
__device__ int2    g_pri_pack[EE];     // {src, half2(c1,c2) bits}
__device__ int2    g_sup_pack[EE];     // {src, f32 cbits}

// ---------------- combined: linear (blocks [0,LINB)) + degree count ------------
// R11 pairing (validated best): linear 256 rows/block, one thread per row,
// 114 regs; count blocks tolerate the occupancy hit. Never pair with fill (R12),
// never split rows across thread pairs (R15).
__global__ void count_linear_kernel(const int* __restrict__ pri,
                                    const int* __restrict__ sup,
                                    const float* __restrict__ x,
                                    const float* __restrict__ w1,
                                    const float* __restrict__ b1,
                                    const float* __restrict__ w2,
                                    const float* __restrict__ b2,
                                    __half2* __restrict__ o1,
                                    __half2* __restrict__ o2) {
    __shared__ unsigned long long wt2[FF][H2];   // 32 KB
    __shared__ float bs[HH];

    if (blockIdx.x >= LINB) {
        int i = (blockIdx.x - LINB) * blockDim.x + threadIdx.x;
        if (i < EE) {
            atomicAdd(&g_cnt[pri[EE + i]], 1);
        } else if (i < 2 * EE) {
            atomicAdd(&g_cnt[NN + sup[i]], 1);
        }
        return;
    }

    int set = blockIdx.x & 1;
    int rowblk = blockIdx.x >> 1;
    const float* w  = set ? w2 : w1;
    const float* b  = set ? b2 : b1;
    __half2* outp   = set ? o2 : o1;

    int tid = threadIdx.x;
    for (int idx = tid; idx < FF * H2; idx += 256) {
        int p = idx & (H2 - 1);
        int f = idx >> 5;
        unsigned long long pk;
        float lo = w[(2 * p) * FF + f];
        float hi = w[(2 * p + 1) * FF + f];
        asm("mov.b64 %0, {%1, %2};" : "=l"(pk) : "f"(lo), "f"(hi));
        wt2[f][p] = pk;
    }
    if (tid < HH) bs[tid] = b[tid];
    __syncthreads();

    int row = rowblk * 256 + tid;
    if (row >= NN) return;

    unsigned long long acc2[H2];
#pragma unroll
    for (int p = 0; p < H2; p++)
        asm("mov.b64 %0, {%1, %2};" : "=l"(acc2[p]) : "f"(bs[2 * p]), "f"(bs[2 * p + 1]));

    const float4* xr = reinterpret_cast<const float4*>(x + (size_t)row * FF);
#pragma unroll 2
    for (int f4 = 0; f4 < FF / 4; f4++) {
        float4 xv = xr[f4];
        float xq[4] = {xv.x, xv.y, xv.z, xv.w};
#pragma unroll
        for (int q = 0; q < 4; q++) {
            int f = f4 * 4 + q;
            unsigned long long xx;
            asm("mov.b64 %0, {%1, %1};" : "=l"(xx) : "f"(xq[q]));
            const ulonglong2* wrow = reinterpret_cast<const ulonglong2*>(&wt2[f][0]);
#pragma unroll
            for (int k8 = 0; k8 < H2 / 2; k8++) {
                ulonglong2 wv = wrow[k8];
                asm("fma.rn.f32x2 %0, %1, %2, %0;" : "+l"(acc2[2 * k8])     : "l"(wv.x), "l"(xx));
                asm("fma.rn.f32x2 %0, %1, %2, %0;" : "+l"(acc2[2 * k8 + 1]) : "l"(wv.y), "l"(xx));
            }
        }
    }

    union { __half2 h2[H2]; uint4 u4[H2 / 4]; } P;
#pragma unroll
    for (int p = 0; p < H2; p++) {
        float lo, hi;
        asm("mov.b64 {%0, %1}, %2;" : "=f"(lo), "=f"(hi) : "l"(acc2[p]));
        P.h2[p] = __floats2half2_rn(lo, hi);
    }
    uint4* op = reinterpret_cast<uint4*>(outp + (size_t)row * H2);
#pragma unroll
    for (int q = 0; q < H2 / 4; q++) op[q] = P.u4[q];
}

// ---------------- scan part 1 + fused dinv --------------------------------------
__global__ void scan1_kernel() {
    __shared__ int sh[SCAN_B];
    int seg = blockIdx.y;
    int i = blockIdx.x * SCAN_B + threadIdx.x;
    int v = (i < NN) ? g_cnt[seg * NN + i] : 0;

    if (seg == 0 && i < NN) {
        float cp = (float)v;
        float cs = (float)g_cnt[NN + i];
        float d1 = rsqrtf(cp + 0.3f);
        float d2 = rsqrtf(cp + 0.5f);
        g_dinv[i]          = d1;
        g_dinv[NN + i]     = d2;
        g_dinv[2 * NN + i] = rsqrtf(cs + 0.5f);
        __half2 h = __floats2half2_rn(d1, d2);
        g_dinvh[i] = *reinterpret_cast<unsigned*>(&h);
    }

    sh[threadIdx.x] = v;
    __syncthreads();
    for (int off = 1; off < SCAN_B; off <<= 1) {
        int t = (threadIdx.x >= off) ? sh[threadIdx.x - off] : 0;
        __syncthreads();
        sh[threadIdx.x] += t;
        __syncthreads();
    }
    if (i < NN) g_rowptr[seg * NN + i] = sh[threadIdx.x] - v;
    if (threadIdx.x == SCAN_B - 1) g_bsum[seg * NBLK + blockIdx.x] = sh[threadIdx.x];
}

// ---------------- scan part 2+3 -------------------------------------------------
__global__ void scan23_kernel() {
    int seg = blockIdx.y;
    int t = threadIdx.x;
    __shared__ int warpsum[32];
    __shared__ int soff;

    int p = (t < NBLK && t < blockIdx.x) ? g_bsum[seg * NBLK + t] : 0;
    for (int o = 16; o; o >>= 1) p += __shfl_down_sync(0xffffffffu, p, o);
    if ((t & 31) == 0) warpsum[t >> 5] = p;
    __syncthreads();
    if (t < 32) {
        int v = warpsum[t];
        for (int o = 16; o; o >>= 1) v += __shfl_down_sync(0xffffffffu, v, o);
        if (t == 0) soff = v;
    }
    __syncthreads();

    int i = blockIdx.x * SCAN_B + t;
    if (i < NN) {
        int rp = g_rowptr[seg * NN + i] + soff;
        g_rowptr[seg * NN + i] = rp;
        g_cursor[seg * NN + i] = rp;
    }
}

// ---------------- fill (standalone; pri coef = prepacked half2, 8 B record) -----
__global__ void fill_kernel(const int* __restrict__ pri,
                            const int* __restrict__ sup) {
    int i = blockIdx.x * blockDim.x + threadIdx.x;
    if (i < EE) {
        int r = pri[i], c = pri[EE + i];
        int pos = atomicAdd(&g_cursor[c], 1);
        g_pri_pack[pos] = make_int2(r, (int)g_dinvh[r]);
    } else if (i < 2 * EE) {
        int e = i - EE;
        int r = sup[e], c = sup[EE + e];
        int pos = atomicAdd(&g_cursor[NN + c], 1);
        g_sup_pack[pos] = make_int2(r, __float_as_int(g_dinv[2 * NN + r]));
    }
}

// ---------------- hop helpers ---------------------------------------------------
__device__ __forceinline__ void acc_row(float2 (&acc)[4], uint4 v, float cf) {
    union { uint4 u; __half2 h2[4]; } U; U.u = v;
#pragma unroll
    for (int q = 0; q < 4; q++) {
        float2 f = __half22float2(U.h2[q]);
        acc[q].x += cf * f.x;
        acc[q].y += cf * f.y;
    }
}
__device__ __forceinline__ void self_scale(float2 (&acc)[4], uint4 v, float s) {
    union { uint4 u; __half2 h2[4]; } U; U.u = v;
#pragma unroll
    for (int q = 0; q < 4; q++) {
        float2 f = __half22float2(U.h2[q]);
        acc[q].x = s * f.x;
        acc[q].y = s * f.y;
    }
}
__device__ __forceinline__ uint4 pack_row(const float2 (&acc)[4]) {
    union { __half2 h2[4]; uint4 u; } P;
#pragma unroll
    for (int q = 0; q < 4; q++) P.h2[q] = __float22half2_rn(acc[q]);
    return P.u;
}
__device__ __forceinline__ float2 unpack_coef(int bits) {
    __half2 h = *reinterpret_cast<__half2*>(&bits);
    return __half22float2(h);
}

// ---------------- P1: hop1 -------------------------------------------------------
struct FusedArgs {
    const int2* pack;      // {src, half2 coef bits}
    const int*  rowptr;
    const int*  cnt;
    const float* dinvA;
    const float* dinvC;
    const uint4* hA;
    const uint4* hC;
    uint4* outA;
    uint4* outC;
};
struct SupArgs {
    const int2* pack;      // {src, f32 cbits}
    const int*  rowptr;
    const int*  cnt;
    const float* dinv;
    const uint4* h;
    uint4* out;
};

__device__ __forceinline__ void hop1_fused(const FusedArgs A) {
    int warp = blockIdx.x * (blockDim.x >> 5) + (threadIdx.x >> 5);
    int lane = threadIdx.x & 31;
    int g = lane >> 3, i = lane & 7;
    int c = warp * 4 + g;

    float dcA = A.dinvA[c], dcC = A.dinvC[c];
    float sA = 0.7f + 0.3f * dcA * dcA;
    float sC = 0.5f + 0.5f * dcC * dcC;

    float2 accA[4], accC[4];
    self_scale(accA, A.hA[(size_t)c * 8 + i], sA);
    self_scale(accC, A.hC[(size_t)c * 8 + i], sC);

    int start = A.rowptr[c];
    int n = A.cnt[c];
    int nmax = __reduce_max_sync(0xffffffffu, n);

    for (int base = 0; base < nmax; base += 8) {
        int2 e = make_int2(0, 0);
        if (i < n - base) e = A.pack[start + base + i];
        int jmax = nmax - base;
        if (jmax >= 8) {
#pragma unroll
            for (int j = 0; j < 8; j++) {
                int rj = __shfl_sync(0xffffffffu, e.x, j, 8);
                int cb = __shfl_sync(0xffffffffu, e.y, j, 8);
                float2 dd = unpack_coef(cb);
                float cf1 = dd.x * dcA;
                float cf2 = dd.y * dcC;
                uint4 vA = A.hA[(size_t)rj * 8 + i];
                uint4 vC = A.hC[(size_t)rj * 8 + i];
                acc_row(accA, vA, cf1);
                acc_row(accC, vC, cf2);
            }
        } else {
            for (int j = 0; j < jmax; j++) {
                int rj = __shfl_sync(0xffffffffu, e.x, j, 8);
                int cb = __shfl_sync(0xffffffffu, e.y, j, 8);
                float2 dd = unpack_coef(cb);
                float cf1 = dd.x * dcA;
                float cf2 = dd.y * dcC;
                uint4 vA = A.hA[(size_t)rj * 8 + i];
                uint4 vC = A.hC[(size_t)rj * 8 + i];
                acc_row(accA, vA, cf1);
                acc_row(accC, vC, cf2);
            }
        }
    }

    A.outA[(size_t)c * 8 + i] = pack_row(accA);
    A.outC[(size_t)c * 8 + i] = pack_row(accC);
}

__device__ __forceinline__ void hop1_sup(const SupArgs A) {
    int warp = blockIdx.x * (blockDim.x >> 5) + (threadIdx.x >> 5);
    int lane = threadIdx.x & 31;
    int g = lane >> 3, i = lane & 7;
    int c = warp * 4 + g;

    float dc = A.dinv[c];
    float s = 0.5f + 0.5f * dc * dc;

    float2 acc[4];
    self_scale(acc, A.h[(size_t)c * 8 + i], s);

    int start = A.rowptr[c];
    int n = A.cnt[c];
    int nmax = __reduce_max_sync(0xffffffffu, n);

    for (int base = 0; base < nmax; base += 8) {
        int2 e = make_int2(0, 0);
        if (i < n - base) e = A.pack[start + base + i];
        int jmax = nmax - base;
        if (jmax >= 8) {
#pragma unroll
            for (int j = 0; j < 8; j++) {
                int   rj = __shfl_sync(0xffffffffu, e.x, j, 8);
                float cf = __int_as_float(__shfl_sync(0xffffffffu, e.y, j, 8)) * dc;
                uint4 v = A.h[(size_t)rj * 8 + i];
                acc_row(acc, v, cf);
            }
        } else {
            for (int j = 0; j < jmax; j++) {
                int   rj = __shfl_sync(0xffffffffu, e.x, j, 8);
                float cf = __int_as_float(__shfl_sync(0xffffffffu, e.y, j, 8)) * dc;
                uint4 v = A.h[(size_t)rj * 8 + i];
                acc_row(acc, v, cf);
            }
        }
    }

    A.out[(size_t)c * 8 + i] = pack_row(acc);
}

__global__ void hop1_kernel(FusedArgs fa, SupArgs sa) {
    if (blockIdx.y == 0) hop1_fused(fa);
    else                 hop1_sup(sa);
}

// ---------------- P2: hop2, direct fp32 output ----------------------------------
__global__ void hop2_kernel(const int2* __restrict__ ppack,
                            const int*  __restrict__ prp,
                            const int*  __restrict__ pcnt,
                            const int2* __restrict__ spack,
                            const int*  __restrict__ srp,
                            const int*  __restrict__ scnt,
                            const float* __restrict__ dinv,
                            const uint4* __restrict__ hD1,
                            const uint4* __restrict__ hD3,
                            const uint4* __restrict__ hD2,
                            float* __restrict__ z1,
                            float* __restrict__ z2) {
    int warp = blockIdx.x * (blockDim.x >> 5) + (threadIdx.x >> 5);
    int lane = threadIdx.x & 31;
    int g = lane >> 3, i = lane & 7;
    int c = warp * 4 + g;

    float dcA = dinv[c];
    float dcC = dinv[NN + c];
    float dcS = dinv[2 * NN + c];
    float sA = 0.7f + 0.3f * dcA * dcA;
    float sC = 0.5f + 0.5f * dcC * dcC;
    float sS = 0.5f + 0.5f * dcS * dcS;

    float2 accA[4], accC[4];
    self_scale(accA, hD1[(size_t)c * 8 + i], sA);
    self_scale(accC, hD3[(size_t)c * 8 + i], sC);

    {
        int start = prp[c];
        int n = pcnt[c];
        int nmax = __reduce_max_sync(0xffffffffu, n);
        for (int base = 0; base < nmax; base += 8) {
            int2 e = make_int2(0, 0);
            if (i < n - base) e = ppack[start + base + i];
            int jmax = nmax - base;
            if (jmax >= 8) {
#pragma unroll
                for (int j = 0; j < 8; j++) {
                    int rj = __shfl_sync(0xffffffffu, e.x, j, 8);
                    int cb = __shfl_sync(0xffffffffu, e.y, j, 8);
                    float2 dd = unpack_coef(cb);
                    float cf1 = dd.x * dcA;
                    float cf2 = dd.y * dcC;
                    uint4 vA = hD1[(size_t)rj * 8 + i];
                    uint4 vC = hD3[(size_t)rj * 8 + i];
                    acc_row(accA, vA, cf1);
                    acc_row(accC, vC, cf2);
                }
            } else {
                for (int j = 0; j < jmax; j++) {
                    int rj = __shfl_sync(0xffffffffu, e.x, j, 8);
                    int cb = __shfl_sync(0xffffffffu, e.y, j, 8);
                    float2 dd = unpack_coef(cb);
                    float cf1 = dd.x * dcA;
                    float cf2 = dd.y * dcC;
                    uint4 vA = hD1[(size_t)rj * 8 + i];
                    uint4 vC = hD3[(size_t)rj * 8 + i];
                    acc_row(accA, vA, cf1);
                    acc_row(accC, vC, cf2);
                }
            }
        }
    }

    {
        float4* op = reinterpret_cast<float4*>(z1 + (size_t)c * HH + i * 8);
        op[0] = make_float4(accA[0].x, accA[0].y, accA[1].x, accA[1].y);
        op[1] = make_float4(accA[2].x, accA[2].y, accA[3].x, accA[3].y);
    }

    {
        float2 accS[4];
        self_scale(accS, hD2[(size_t)c * 8 + i], sS);

        int start = srp[c];
        int n = scnt[c];
        int nmax = __reduce_max_sync(0xffffffffu, n);
        for (int base = 0; base < nmax; base += 8) {
            int2 e = make_int2(0, 0);
            if (i < n - base) e = spack[start + base + i];
            int jmax = nmax - base;
            if (jmax >= 8) {
#pragma unroll
                for (int j = 0; j < 8; j++) {
                    int   rj = __shfl_sync(0xffffffffu, e.x, j, 8);
                    float cf = __int_as_float(__shfl_sync(0xffffffffu, e.y, j, 8)) * dcS;
                    uint4 v = hD2[(size_t)rj * 8 + i];
                    acc_row(accS, v, cf);
                }
            } else {
                for (int j = 0; j < jmax; j++) {
                    int   rj = __shfl_sync(0xffffffffu, e.x, j, 8);
                    float cf = __int_as_float(__shfl_sync(0xffffffffu, e.y, j, 8)) * dcS;
                    uint4 v = hD2[(size_t)rj * 8 + i];
                    acc_row(accS, v, cf);
                }
            }
        }

#pragma unroll
        for (int q = 0; q < 4; q++) {
            accC[q].x += accS[q].x;
            accC[q].y += accS[q].y;
        }
    }

    {
        float4* op = reinterpret_cast<float4*>(z2 + (size_t)c * HH + i * 8);
        op[0] = make_float4(accC[0].x, accC[0].y, accC[1].x, accC[1].y);
        op[1] = make_float4(accC[2].x, accC[2].y, accC[3].x, accC[3].y);
    }
}

// ---------------- launch --------------------------------------------------------
extern "C" void kernel_launch(void* const* d_in, const int* in_sizes, int n_in,
                              void* d_out, int out_size) {
    const float* x   = (const float*)d_in[0];
    const int*   pri = (const int*)d_in[1];
    const int*   sup = (const int*)d_in[2];
    const float* w1  = (const float*)d_in[3];
    const float* b1  = (const float*)d_in[4];
    const float* w2  = (const float*)d_in[5];
    const float* b2  = (const float*)d_in[6];
    float* out = (float*)d_out;

    __half2 *bufA, *bufC, *bufD1, *bufD2, *bufD3;
    float *dinv;
    int *cnt, *rowptr;
    int2 *pri_pack, *sup_pack;
    cudaGetSymbolAddress((void**)&bufA, g_bufA);
    cudaGetSymbolAddress((void**)&bufC, g_bufC);
    cudaGetSymbolAddress((void**)&bufD1, g_bufD1);
    cudaGetSymbolAddress((void**)&bufD2, g_bufD2);
    cudaGetSymbolAddress((void**)&bufD3, g_bufD3);
    cudaGetSymbolAddress((void**)&dinv, g_dinv);
    cudaGetSymbolAddress((void**)&cnt, g_cnt);
    cudaGetSymbolAddress((void**)&rowptr, g_rowptr);
    cudaGetSymbolAddress((void**)&pri_pack, g_pri_pack);
    cudaGetSymbolAddress((void**)&sup_pack, g_sup_pack);

    const int TPB = 256;

    cudaMemsetAsync(cnt, 0, 2 * NN * sizeof(int));

    // combined linear + degree count (validated R11 pairing)
    count_linear_kernel<<<LINB + CNTB, TPB>>>(pri, sup, x, w1, b1, w2, b2,
                                              bufA, bufC);

    scan1_kernel<<<dim3(NBLK, 2), SCAN_B>>>();
    scan23_kernel<<<dim3(NBLK, 2), SCAN_B>>>();
    fill_kernel<<<CNTB, TPB>>>(pri, sup);

    float* z1 = out;
    float* z2 = out + (size_t)NN * HH;
    const int gridHopX = NN / 32;

    FusedArgs f1 = {pri_pack, rowptr, cnt, dinv, dinv + NN,
                    (const uint4*)bufA, (const uint4*)bufC,
                    (uint4*)bufD1, (uint4*)bufD3};
    SupArgs   s1 = {sup_pack, rowptr + NN, cnt + NN, dinv + 2 * NN,
                    (const uint4*)bufC, (uint4*)bufD2};
    hop1_kernel<<<dim3(gridHopX, 2), TPB>>>(f1, s1);

    hop2_kernel<<<gridHopX, TPB>>>(pri_pack, rowptr, cnt,
                                   sup_pack, rowptr + NN, cnt + NN,
                                   dinv,
                                   (const uint4*)bufD1, (const uint4*)bufD3,
                                   (const uint4*)bufD2,
                                   z1, z2);
}